// round 14
// baseline (speedup 1.0000x reference)
#include <cuda_runtime.h>
#include <cuda_bf16.h>
#include <cstdint>

#define S 1024
#define B 8192
#define EPSF 1e-8f
#define THREADS 256
#define SEG 128              // timesteps per warp segment
#define LPT 4                // timesteps per lane
#define WPR 8                // warps per row
#define NBLK B               // 1 row per block

// accurate tanh: rel err ~1e-7, ~6 instructions
__device__ __forceinline__ float tanh_acc(float x) {
    float e = __expf(2.0f * x);
    return 1.0f - __fdividef(2.0f, e + 1.0f);
}

__device__ __forceinline__ void cp_async4(void* smem_dst, const void* gmem_src) {
    unsigned int s = (unsigned int)__cvta_generic_to_shared(smem_dst);
    asm volatile("cp.async.ca.shared.global [%0], [%1], 4;" :: "r"(s), "l"(gmem_src));
}

// Two-level parallel reverse affine scan: 8 warps per row, 128-step segment
// per warp, 4 timesteps per lane. Inline tables; v staged in smem with a
// layout that allows a single aligned conflict-free LDS.128 per thread.
__global__ __launch_bounds__(THREADS, 8)
void td_lambda_kernel(const float* __restrict__ raw_gamma,
                      const float* __restrict__ raw_lambd,
                      const float* __restrict__ values,
                      const float* __restrict__ rewards,
                      const int*   __restrict__ dones,
                      float* __restrict__ out)
{
    // offset(t) = t + 4*(t>>5); max 139 -> 144 floats/warp, 16B-aligned
    __shared__ __align__(16) float s_v[WPR][SEG + 16];
    __shared__ float s_cA[WPR], s_cB[WPR];
    __shared__ float s_part[THREADS];            // srw scratch

    const int tid  = threadIdx.x;
    const int lane = tid & 31;
    const int warp = tid >> 5;

    if (blockIdx.x < NBLK) {
        const int b   = blockIdx.x;
        const int seg = warp;                    // 0..7
        const float* __restrict__ rrow = rewards + (size_t)b * S;
        const int*   __restrict__ drow = dones   + (size_t)b * S;
        const float* __restrict__ vrow = values  + (size_t)b * (S + 1);
        float* __restrict__ orow = out + (size_t)b * S;

        const int segbase = seg * SEG;
        const int base    = segbase + lane * LPT;

        // ---- v: gmem -> padded smem via cp.async (store at lane + 36k) ----
        #pragma unroll
        for (int k = 0; k < 4; ++k)
            cp_async4(&s_v[warp][lane + 36 * k],
                      vrow + segbase + 1 + lane + 32 * k);
        asm volatile("cp.async.commit_group;");

        // ---- r/d/lambda loads while copies fly ----
        float4 r4 = __ldcs((const float4*)(rrow + base));
        int4   d4 = __ldcs((const int4*)(drow + base));
        float4 rl4 = *(const float4*)(raw_lambd + base);
        const float vS = __ldg(&vrow[S]);

        // ---- inline tables: gamma + 4 lambdas (tanh > EPS for all inputs) ----
        const float gamma = tanh_acc(raw_gamma[0]);
        float ga[LPT], gb[LPT];
        {
            float lam[LPT] = {tanh_acc(rl4.x), tanh_acc(rl4.y),
                              tanh_acc(rl4.z), tanh_acc(rl4.w)};
            #pragma unroll
            for (int j = 0; j < LPT; ++j) {
                ga[j] = gamma * lam[j];
                gb[j] = gamma * (1.0f - lam[j]);
            }
        }

        asm volatile("cp.async.wait_group 0;");
        __syncwarp();

        float r[LPT]  = {r4.x, r4.y, r4.z, r4.w};
        int   dn[LPT] = {d4.x, d4.y, d4.z, d4.w};
        // single aligned LDS.128, conflict-free
        float4 v4 = *(const float4*)&s_v[warp][lane * LPT + 4 * (lane >> 3)];
        float v[LPT] = {v4.x, v4.y, v4.z, v4.w};

        float a[LPT], bb[LPT];
        #pragma unroll
        for (int j = 0; j < LPT; ++j) {
            bool z = (dn[j] != 0);
            a[j]  = z ? 0.0f : ga[j];
            bb[j] = z ? r[j] : fmaf(gb[j], v[j], r[j]);
        }

        // local composition G = F_j0 ∘ ... ∘ F_j3
        float A = a[LPT - 1], Bc = bb[LPT - 1];
        #pragma unroll
        for (int j = LPT - 2; j >= 0; --j) {
            Bc = fmaf(a[j], Bc, bb[j]);
            A  = a[j] * A;
        }

        // warp suffix scan of lane composites
        float sA = A, sB = Bc;
        #pragma unroll
        for (int off = 1; off < 32; off <<= 1) {
            float a2 = __shfl_down_sync(0xffffffffu, sA, off);
            float b2 = __shfl_down_sync(0xffffffffu, sB, off);
            if (lane + off < 32) {
                sB = fmaf(sA, b2, sB);
                sA = sA * a2;
            }
        }

        if (lane == 0) { s_cA[warp] = sA; s_cB[warp] = sB; }
        __syncthreads();

        // entry carry: apply composites of segments seg+1..7 to v_S
        float carry = vS;
        #pragma unroll
        for (int k = WPR - 1; k >= 1; --k) {
            if (k > seg)
                carry = fmaf(s_cA[k], carry, s_cB[k]);
        }

        float eA = __shfl_down_sync(0xffffffffu, sA, 1);
        float eB = __shfl_down_sync(0xffffffffu, sB, 1);
        if (lane == 31) { eA = 1.0f; eB = 0.0f; }
        float x = fmaf(eA, carry, eB);

        float o[LPT];
        #pragma unroll
        for (int j = LPT - 1; j >= 0; --j) {
            x = fmaf(a[j], x, bb[j]);
            o[j] = x;
        }
        __stcs((float4*)(orow + base), make_float4(o[0], o[1], o[2], o[3]));
    } else {
        // ---------------- srw (sum_reward_weights) ----------------
        float* s_w = &s_v[0][0];   // 8*144 = 1152 contiguous floats >= S
        const float gamma = tanh_acc(raw_gamma[0]);

        if (tid < 32) {
            float carry = 1.0f;
            for (int c = S / 32 - 1; c >= 0; --c) {
                const int t = c * 32 + lane;
                float lam = tanh_acc(raw_lambd[t]);
                float a  = gamma * lam;
                float bb = gamma * (1.0f - lam);
                #pragma unroll
                for (int off = 1; off < 32; off <<= 1) {
                    float a2 = __shfl_down_sync(0xffffffffu, a,  off);
                    float b2 = __shfl_down_sync(0xffffffffu, bb, off);
                    if (lane + off < 32) {
                        bb = fmaf(a, b2, bb);
                        a  = a * a2;
                    }
                }
                float vv = fmaf(a, carry, bb);
                s_w[t] = fmaxf(1.0f - vv, EPSF);
                carry = __shfl_sync(0xffffffffu, vv, 0);
            }
        }
        __syncthreads();

        float ps = 0.0f;
        for (int i = tid; i < S; i += THREADS) ps += s_w[i];
        s_part[tid] = ps;
        __syncthreads();
        for (int stride = THREADS / 2; stride > 0; stride >>= 1) {
            if (tid < stride) s_part[tid] += s_part[tid + stride];
            __syncthreads();
        }
        float mean = s_part[0] * (1.0f / (float)S);
        float inv  = 1.0f / fmaxf(mean, EPSF);
        for (int i = tid; i < S; i += THREADS)
            out[(size_t)B * S + i] = s_w[i] * inv;
    }
}

extern "C" void kernel_launch(void* const* d_in, const int* in_sizes, int n_in,
                              void* d_out, int out_size) {
    const float* raw_gamma = (const float*)d_in[0];
    const float* raw_lambd = (const float*)d_in[1];
    const float* values    = (const float*)d_in[2];
    const float* rewards   = (const float*)d_in[3];
    const int*   dones     = (const int*)d_in[4];
    float* out = (float*)d_out;

    td_lambda_kernel<<<NBLK + 1, THREADS>>>(raw_gamma, raw_lambd, values,
                                            rewards, dones, out);
}

// round 15
// speedup vs baseline: 1.5293x; 1.5293x over previous
#include <cuda_runtime.h>
#include <cuda_bf16.h>
#include <cstdint>

#define S 1024
#define B 8192
#define EPSF 1e-8f
#define THREADS 256
#define SEG 128              // timesteps per warp segment
#define LPT 4                // timesteps per lane
#define WPR 8                // warps per row
#define NBLK B               // 1 row per block

// accurate tanh: rel err ~1e-7, ~6 instructions
__device__ __forceinline__ float tanh_acc(float x) {
    float e = __expf(2.0f * x);
    return 1.0f - __fdividef(2.0f, e + 1.0f);
}

__device__ __forceinline__ void cp_async4(void* smem_dst, const void* gmem_src) {
    unsigned int s = (unsigned int)__cvta_generic_to_shared(smem_dst);
    asm volatile("cp.async.ca.shared.global [%0], [%1], 4;" :: "r"(s), "l"(gmem_src));
}

// Two-level parallel reverse affine scan: 8 warps per row, 128-step segment
// per warp, 4 timesteps per lane. Inline tables (no setup kernel); v staged
// via cp.async into the proven 33-stride padded smem layout.
__global__ __launch_bounds__(THREADS, 8)
void td_lambda_kernel(const float* __restrict__ raw_gamma,
                      const float* __restrict__ raw_lambd,
                      const float* __restrict__ values,
                      const float* __restrict__ rewards,
                      const int*   __restrict__ dones,
                      float* __restrict__ out)
{
    __shared__ float s_v[WPR][SEG + SEG / 32];   // 8 x 132, padded (33-stride)
    __shared__ float s_cA[WPR], s_cB[WPR];
    __shared__ float s_part[THREADS];            // srw scratch

    const int tid  = threadIdx.x;
    const int lane = tid & 31;
    const int warp = tid >> 5;

    if (blockIdx.x < NBLK) {
        const int b   = blockIdx.x;
        const int seg = warp;                    // 0..7
        const float* __restrict__ rrow = rewards + (size_t)b * S;
        const int*   __restrict__ drow = dones   + (size_t)b * S;
        const float* __restrict__ vrow = values  + (size_t)b * (S + 1);
        float* __restrict__ orow = out + (size_t)b * S;

        const int segbase = seg * SEG;
        const int base    = segbase + lane * LPT;

        // ---- v: gmem -> padded smem via cp.async ----
        #pragma unroll
        for (int k = 0; k < 4; ++k)
            cp_async4(&s_v[warp][lane + 33 * k],
                      vrow + segbase + 1 + lane + 32 * k);
        asm volatile("cp.async.commit_group;");

        // ---- r/d/lambda loads while copies fly ----
        float4 r4 = __ldcs((const float4*)(rrow + base));
        int4   d4 = __ldcs((const int4*)(drow + base));
        float4 rl4 = *(const float4*)(raw_lambd + base);
        const float vS = __ldg(&vrow[S]);

        // ---- inline tables: gamma + 4 lambdas (tanh > EPS for all inputs) ----
        const float gamma = tanh_acc(raw_gamma[0]);
        float ga[LPT], gb[LPT];
        {
            float lam[LPT] = {tanh_acc(rl4.x), tanh_acc(rl4.y),
                              tanh_acc(rl4.z), tanh_acc(rl4.w)};
            #pragma unroll
            for (int j = 0; j < LPT; ++j) {
                ga[j] = gamma * lam[j];
                gb[j] = gamma * (1.0f - lam[j]);
            }
        }

        asm volatile("cp.async.wait_group 0;");
        __syncwarp();

        float r[LPT]  = {r4.x, r4.y, r4.z, r4.w};
        int   dn[LPT] = {d4.x, d4.y, d4.z, d4.w};
        // conflict-free scalar reads: bank(4l + l>>3) distinct over lanes
        const float* vbuf = &s_v[warp][lane * LPT + (lane >> 3)];

        float a[LPT], bb[LPT];
        #pragma unroll
        for (int j = 0; j < LPT; ++j) {
            float v = vbuf[j];
            bool  z = (dn[j] != 0);
            a[j]  = z ? 0.0f : ga[j];
            bb[j] = z ? r[j] : fmaf(gb[j], v, r[j]);
        }

        // local composition G = F_j0 ∘ ... ∘ F_j3
        float A = a[LPT - 1], Bc = bb[LPT - 1];
        #pragma unroll
        for (int j = LPT - 2; j >= 0; --j) {
            Bc = fmaf(a[j], Bc, bb[j]);
            A  = a[j] * A;
        }

        // warp suffix scan of lane composites
        float sA = A, sB = Bc;
        #pragma unroll
        for (int off = 1; off < 32; off <<= 1) {
            float a2 = __shfl_down_sync(0xffffffffu, sA, off);
            float b2 = __shfl_down_sync(0xffffffffu, sB, off);
            if (lane + off < 32) {
                sB = fmaf(sA, b2, sB);
                sA = sA * a2;
            }
        }

        if (lane == 0) { s_cA[warp] = sA; s_cB[warp] = sB; }
        __syncthreads();

        // entry carry: apply composites of segments seg+1..7 to v_S
        float carry = vS;
        #pragma unroll
        for (int k = WPR - 1; k >= 1; --k) {
            if (k > seg)
                carry = fmaf(s_cA[k], carry, s_cB[k]);
        }

        float eA = __shfl_down_sync(0xffffffffu, sA, 1);
        float eB = __shfl_down_sync(0xffffffffu, sB, 1);
        if (lane == 31) { eA = 1.0f; eB = 0.0f; }
        float x = fmaf(eA, carry, eB);

        float o[LPT];
        #pragma unroll
        for (int j = LPT - 1; j >= 0; --j) {
            x = fmaf(a[j], x, bb[j]);
            o[j] = x;
        }
        __stcs((float4*)(orow + base), make_float4(o[0], o[1], o[2], o[3]));
    } else {
        // ---------------- srw (sum_reward_weights) ----------------
        float* s_w = &s_v[0][0];   // 1056 contiguous floats >= S
        const float gamma = tanh_acc(raw_gamma[0]);

        if (tid < 32) {
            float carry = 1.0f;
            for (int c = S / 32 - 1; c >= 0; --c) {
                const int t = c * 32 + lane;
                float lam = tanh_acc(raw_lambd[t]);
                float a  = gamma * lam;
                float bb = gamma * (1.0f - lam);
                #pragma unroll
                for (int off = 1; off < 32; off <<= 1) {
                    float a2 = __shfl_down_sync(0xffffffffu, a,  off);
                    float b2 = __shfl_down_sync(0xffffffffu, bb, off);
                    if (lane + off < 32) {
                        bb = fmaf(a, b2, bb);
                        a  = a * a2;
                    }
                }
                float vv = fmaf(a, carry, bb);
                s_w[t] = fmaxf(1.0f - vv, EPSF);
                carry = __shfl_sync(0xffffffffu, vv, 0);
            }
        }
        __syncthreads();

        float ps = 0.0f;
        for (int i = tid; i < S; i += THREADS) ps += s_w[i];
        s_part[tid] = ps;
        __syncthreads();
        for (int stride = THREADS / 2; stride > 0; stride >>= 1) {
            if (tid < stride) s_part[tid] += s_part[tid + stride];
            __syncthreads();
        }
        float mean = s_part[0] * (1.0f / (float)S);
        float inv  = 1.0f / fmaxf(mean, EPSF);
        for (int i = tid; i < S; i += THREADS)
            out[(size_t)B * S + i] = s_w[i] * inv;
    }
}

extern "C" void kernel_launch(void* const* d_in, const int* in_sizes, int n_in,
                              void* d_out, int out_size) {
    const float* raw_gamma = (const float*)d_in[0];
    const float* raw_lambd = (const float*)d_in[1];
    const float* values    = (const float*)d_in[2];
    const float* rewards   = (const float*)d_in[3];
    const int*   dones     = (const int*)d_in[4];
    float* out = (float*)d_out;

    td_lambda_kernel<<<NBLK + 1, THREADS>>>(raw_gamma, raw_lambd, values,
                                            rewards, dones, out);
}